// round 15
// baseline (speedup 1.0000x reference)
#include <cuda_runtime.h>
#include <cuda_fp16.h>
#include <mma.h>
#include <math.h>

// ---------------------------------------------------------------------------
// Problem constants
//   G=8192 gaussians, BS=1, 3 tokens, GFD=32, ATTN=512, H=8 heads, HD=64
//   image_features [256,64,64], K = 12 sample points (6 fixed + 6 learned)
// ---------------------------------------------------------------------------
#define NG      8192
#define NROW    (NG*3)        // 24576 (gaussian,token) rows
#define ATTN    512
#define GFD     32
#define NHEAD   8
#define HDIM    64
#define IMGW    64
#define IMGH    64
#define NPIX    (IMGW*IMGH)   // 4096
#define CIMG    256
#define NK      12

using namespace nvcuda;

// Scratch (static device globals: allocation-free per harness rules)
// g_kvh layout: per pixel, 256 channel-pairs; slot 2p = K half2 (ch 2p,2p+1),
//               slot 2p+1 = V half2.  One 8-byte load fetches K+V for a lane.
__device__ __half2 g_kvh[NPIX * 512];        // 8 MB, L2-resident
__device__ __half2 g_qh[NROW * ATTN / 2];    // q_full, fp16               (25 MB)
__device__ __half2 g_attnh[NROW * ATTN / 2]; // attention output, fp16     (25 MB)
__device__ uint4   g_wh[NG * NHEAD * NK];    // 4 corner weights, each replicated half2
__device__ int4    g_o4[NG * NHEAD * NK];    // clamped corner offsets (x512)

// fp16 operand buffers for tensor-core GEMMs
__device__ __align__(128) __half g_kvw16[1024 * CIMG];   // Wk;Wv rows [a][k]
__device__ __align__(128) __half g_img16[CIMG * NPIX];   // [k][pix]
__device__ __align__(128) __half g_feat16[NROW * GFD];   // [row][f]
__device__ __align__(128) __half g_wq16[GFD * ATTN];     // [f][a]

__constant__ float c_fix[6][3] = {
    {0.f,0.f,0.f},{1.f,0.f,0.f},{0.f,1.f,0.f},
    {0.f,0.f,1.f},{-1.f,0.f,0.f},{0.f,-1.f,0.f}};

__device__ __forceinline__ float sigm_clamped(float x) {
    x = fminf(fmaxf(x, -9.21f), 9.21f);
    return 1.0f / (1.0f + __expf(-x));
}

// 5-stage butterfly warp sum (redux.sync.f32 not available on sm_103 target)
__device__ __forceinline__ float warp_sum(float v) {
    #pragma unroll
    for (int o = 16; o > 0; o >>= 1) v += __shfl_xor_sync(0xffffffffu, v, o);
    return v;
}

// ---------------------------------------------------------------------------
// Kernel 0: fp32 -> fp16 operand conversion (single pass over all GEMM inputs)
// ---------------------------------------------------------------------------
#define N_WKV   (1024 * CIMG)           // 262144
#define N_IMG   (CIMG * NPIX)           // 1048576
#define N_FEAT  (NROW * GFD)            // 786432
#define N_WQ    (GFD * ATTN)            // 16384
#define N_CONV  (N_WKV + N_IMG + N_FEAT + N_WQ)

__global__ void __launch_bounds__(256) convert_fp16(
    const float* __restrict__ Wk, const float* __restrict__ Wv,
    const float* __restrict__ img, const float* __restrict__ feat,
    const float* __restrict__ Wq)
{
    int i = blockIdx.x * 256 + threadIdx.x;
    if (i >= N_CONV) return;
    if (i < N_WKV / 2) {
        g_kvw16[i] = __float2half_rn(Wk[i]);
    } else if (i < N_WKV) {
        g_kvw16[i] = __float2half_rn(Wv[i - N_WKV / 2]);
    } else if (i < N_WKV + N_IMG) {
        int j = i - N_WKV;
        g_img16[j] = __float2half_rn(img[j]);
    } else if (i < N_WKV + N_IMG + N_FEAT) {
        int j = i - N_WKV - N_IMG;
        g_feat16[j] = __float2half_rn(feat[j]);
    } else {
        int j = i - N_WKV - N_IMG - N_FEAT;
        g_wq16[j] = __float2half_rn(Wq[j]);
    }
}

// ---------------------------------------------------------------------------
// Kernel 1: KV maps via tensor cores (wmma m16n16k16, fp16 in, fp32 acc).
//   C[a,pix] = sum_k Wkv16[a,k] * img16[k,pix]
//   Block: 8 warps stacked in a -> 128(a) x 64(pix); warp = 16a x 64pix.
//   Epilogue packs to half2, K/V-interleaved into g_kvh (unchanged layout).
// ---------------------------------------------------------------------------
__global__ void __launch_bounds__(256) kv_gemm_wmma()
{
    __shared__ float sm[128 * 64];
    const int warp = threadIdx.x >> 5;
    const int aBase = blockIdx.y * 128;
    const int pBase = blockIdx.x * 64;

    wmma::fragment<wmma::accumulator, 16, 16, 16, float> c[4];
    #pragma unroll
    for (int j = 0; j < 4; j++) wmma::fill_fragment(c[j], 0.0f);

    const __half* A = g_kvw16 + (size_t)(aBase + warp * 16) * CIMG;
    #pragma unroll
    for (int k0 = 0; k0 < CIMG; k0 += 16) {
        wmma::fragment<wmma::matrix_a, 16, 16, 16, __half, wmma::row_major> a;
        wmma::load_matrix_sync(a, A + k0, CIMG);
        #pragma unroll
        for (int j = 0; j < 4; j++) {
            wmma::fragment<wmma::matrix_b, 16, 16, 16, __half, wmma::row_major> b;
            wmma::load_matrix_sync(b, g_img16 + (size_t)k0 * NPIX + pBase + j * 16, NPIX);
            wmma::mma_sync(c[j], a, b, c[j]);
        }
    }
    #pragma unroll
    for (int j = 0; j < 4; j++)
        wmma::store_matrix_sync(sm + warp * 16 * 64 + j * 16, c[j], 64, wmma::mem_row_major);
    __syncthreads();

    // Pack: 64 channel-pairs x 64 pixels, K/V interleave.
    const bool isK = (aBase < 512);
    const int paBase = aBase >> 1;
    for (int idx = threadIdx.x; idx < 64 * 64; idx += 256) {
        int pal = idx >> 6, pl = idx & 63;
        float lo = sm[(2 * pal) * 64 + pl];
        float hi = sm[(2 * pal + 1) * 64 + pl];
        int pa = paBase + pal;
        int slot = isK ? (2 * pa) : (2 * (pa - 256) + 1);
        g_kvh[(size_t)(pBase + pl) * 512 + slot] = __floats2half2_rn(lo, hi);
    }
}

// ---------------------------------------------------------------------------
// Kernel 2: Q projection via tensor cores.
//   g_qh[row, a] = sum_f feat16[row, f] * Wq16[f, a], K=32 (2 wmma steps).
//   Block: 8 warps stacked in rows -> 128(rows) x 64(cols).
// ---------------------------------------------------------------------------
__global__ void __launch_bounds__(256) q_gemm_wmma()
{
    __shared__ float sm[128 * 64];
    const int warp = threadIdx.x >> 5;
    const int rBase = blockIdx.y * 128;
    const int cBase = blockIdx.x * 64;

    wmma::fragment<wmma::accumulator, 16, 16, 16, float> c[4];
    #pragma unroll
    for (int j = 0; j < 4; j++) wmma::fill_fragment(c[j], 0.0f);

    const __half* A = g_feat16 + (size_t)(rBase + warp * 16) * GFD;
    #pragma unroll
    for (int k0 = 0; k0 < GFD; k0 += 16) {
        wmma::fragment<wmma::matrix_a, 16, 16, 16, __half, wmma::row_major> a;
        wmma::load_matrix_sync(a, A + k0, GFD);
        #pragma unroll
        for (int j = 0; j < 4; j++) {
            wmma::fragment<wmma::matrix_b, 16, 16, 16, __half, wmma::row_major> b;
            wmma::load_matrix_sync(b, g_wq16 + (size_t)k0 * ATTN + cBase + j * 16, ATTN);
            wmma::mma_sync(c[j], a, b, c[j]);
        }
    }
    #pragma unroll
    for (int j = 0; j < 4; j++)
        wmma::store_matrix_sync(sm + warp * 16 * 64 + j * 16, c[j], 64, wmma::mem_row_major);
    __syncthreads();

    // Pack pairs of adjacent channels into g_qh.
    for (int idx = threadIdx.x; idx < 128 * 32; idx += 256) {
        int m = idx >> 5, np = idx & 31;
        __half2 v = __floats2half2_rn(sm[m * 64 + 2 * np], sm[m * 64 + 2 * np + 1]);
        g_qh[((size_t)(rBase + m) * ATTN + cBase + 2 * np) >> 1] = v;
    }
}

// ---------------------------------------------------------------------------
// Kernel 3a: coordinate precompute.
//   One block per gaussian, one warp per head. Computes OffsetNet logits, the
//   12 sample points, and fully-resolved bilinear corner weights (packed as
//   replicated half2) + clamped corner offsets.
// ---------------------------------------------------------------------------
__global__ void __launch_bounds__(256) coord_kernel(
    const float* __restrict__ means, const float* __restrict__ scales,
    const float* __restrict__ rots, const float* __restrict__ transforms,
    const float* __restrict__ proj, const float* __restrict__ W_off,
    const float* __restrict__ b_off)
{
    const int g = blockIdx.x;
    const int tid = threadIdx.x;
    const int h = tid >> 5;
    const int lane = tid & 31;

    __shared__ float sqm[NHEAD][HDIM];   // per-head token-mean query
    __shared__ float slog[NHEAD][18];    // offset logits
    __shared__ float sW[67 * 18];
    __shared__ float sb[18];
    __shared__ float sP[12];
    __shared__ float sMisc[16];          // 0-2 mean_w, 3-11 R(row major), 12-14 scales

    for (int i = tid; i < 67 * 18; i += 256) sW[i] = W_off[i];
    if (tid < 18) sb[tid] = b_off[tid];
    if (tid >= 32 && tid < 44) sP[tid - 32] = proj[tid - 32];
    if (tid == 64) {
        float mx = means[g * 3], my = means[g * 3 + 1], mz = means[g * 3 + 2];
        const float* T = transforms + (size_t)g * 16;
        sMisc[0] = T[0] * mx + T[1] * my + T[2]  * mz + T[3];
        sMisc[1] = T[4] * mx + T[5] * my + T[6]  * mz + T[7];
        sMisc[2] = T[8] * mx + T[9] * my + T[10] * mz + T[11];
        float qw = rots[g * 4], qx = rots[g * 4 + 1], qy = rots[g * 4 + 2], qz = rots[g * 4 + 3];
        float inv = rsqrtf(qw * qw + qx * qx + qy * qy + qz * qz);
        qw *= inv; qx *= inv; qy *= inv; qz *= inv;
        sMisc[3]  = 1.f - 2.f * (qy * qy + qz * qz);
        sMisc[4]  = 2.f * (qx * qy - qw * qz);
        sMisc[5]  = 2.f * (qx * qz + qw * qy);
        sMisc[6]  = 2.f * (qx * qy + qw * qz);
        sMisc[7]  = 1.f - 2.f * (qx * qx + qz * qz);
        sMisc[8]  = 2.f * (qy * qz - qw * qx);
        sMisc[9]  = 2.f * (qx * qz - qw * qy);
        sMisc[10] = 2.f * (qy * qz + qw * qx);
        sMisc[11] = 1.f - 2.f * (qx * qx + qy * qy);
        sMisc[12] = scales[g * 3]; sMisc[13] = scales[g * 3 + 1]; sMisc[14] = scales[g * 3 + 2];
    }

    // per-head token-mean query (2 channels per lane, from fp16 g_qh)
    {
        const __half2* qg = g_qh + ((((size_t)g * 3) * ATTN + h * HDIM) >> 1) + lane;
        float2 q0 = __half22float2(qg[0]);
        float2 q1 = __half22float2(qg[ATTN / 2]);
        float2 q2 = __half22float2(qg[ATTN]);
        sqm[h][lane * 2]     = (q0.x + q1.x + q2.x) * (1.0f / 3.0f);
        sqm[h][lane * 2 + 1] = (q0.y + q1.y + q2.y) * (1.0f / 3.0f);
    }
    __syncthreads();

    // offset logits: off_in = [mean_w(3), q_mean(64)] @ W_off + b_off
    if (lane < 18) {
        float acc = sb[lane] + sMisc[0] * sW[lane] + sMisc[1] * sW[18 + lane] + sMisc[2] * sW[36 + lane];
        #pragma unroll 8
        for (int c = 0; c < HDIM; c++) acc += sqm[h][c] * sW[(3 + c) * 18 + lane];
        slog[h][lane] = acc;
    }
    __syncwarp();

    if (lane < NK) {
        const int k = lane;
        float s0, s1, s2;
        if (k < 6) {
            s0 = c_fix[k][0]; s1 = c_fix[k][1]; s2 = c_fix[k][2];
        } else {
            int b = (k - 6) * 3;
            s0 = sigm_clamped(slog[h][b])     - 0.5f;
            s1 = sigm_clamped(slog[h][b + 1]) - 0.5f;
            s2 = sigm_clamped(slog[h][b + 2]) - 0.5f;
        }
        float o0 = s0 * sMisc[12], o1 = s1 * sMisc[13], o2 = s2 * sMisc[14];
        // world offset = R^T @ o + mean_w
        float wx = sMisc[3] * o0 + sMisc[6] * o1 + sMisc[9]  * o2 + sMisc[0];
        float wy = sMisc[4] * o0 + sMisc[7] * o1 + sMisc[10] * o2 + sMisc[1];
        float wz = sMisc[5] * o0 + sMisc[8] * o1 + sMisc[11] * o2 + sMisc[2];
        float p0 = sP[0] * wx + sP[1] * wy + sP[2]  * wz + sP[3];
        float p1 = sP[4] * wx + sP[5] * wy + sP[6]  * wz + sP[7];
        float p2 = sP[8] * wx + sP[9] * wy + sP[10] * wz + sP[11];
        float z = fmaxf(p2, 1e-5f);
        float xn = fminf(fmaxf(p0 / z * (1.0f / IMGW), 0.0f), 0.9999f);
        float yn = fminf(fmaxf(p1 / z * (1.0f / IMGH), 0.0f), 0.9999f);
        float x = xn * (float)IMGW - 0.5f;
        float y = yn * (float)IMGH - 0.5f;

        // Resolve bilinear sampling: weights (zeroed when OOB, replicated
        // half2) + clamped corner offsets in units of half2 (pixel * 512).
        float xf = floorf(x), yf = floorf(y);
        int x0 = (int)xf, y0 = (int)yf;
        float fx = x - xf, fy = y - yf;
        float w00 = (1.f - fx) * (1.f - fy), w10 = fx * (1.f - fy);
        float w01 = (1.f - fx) * fy,         w11 = fx * fy;
        int x1 = x0 + 1, y1 = y0 + 1;
        float vx0 = (x0 >= 0) ? 1.f : 0.f;
        float vx1 = (x1 <= IMGW - 1) ? 1.f : 0.f;
        float vy0 = (y0 >= 0) ? 1.f : 0.f;
        float vy1 = (y1 <= IMGH - 1) ? 1.f : 0.f;
        int cx0 = max(x0, 0), cx1 = min(x1, IMGW - 1);
        int cy0 = max(y0, 0), cy1 = min(y1, IMGH - 1);

        size_t idx = ((size_t)g * NHEAD + h) * NK + k;
        __half2 h00 = __float2half2_rn(w00 * vx0 * vy0);
        __half2 h10 = __float2half2_rn(w10 * vx1 * vy0);
        __half2 h01 = __float2half2_rn(w01 * vx0 * vy1);
        __half2 h11 = __float2half2_rn(w11 * vx1 * vy1);
        uint4 uw;
        uw.x = *(unsigned*)&h00;
        uw.y = *(unsigned*)&h10;
        uw.z = *(unsigned*)&h01;
        uw.w = *(unsigned*)&h11;
        g_wh[idx] = uw;
        int4 o4;
        o4.x = (cy0 * IMGW + cx0) * 512;
        o4.y = (cy0 * IMGW + cx1) * 512;
        o4.z = (cy1 * IMGW + cx0) * 512;
        o4.w = (cy1 * IMGW + cx1) * 512;
        g_o4[idx] = o4;
    }
}

// ---------------------------------------------------------------------------
// Kernel 3b: gather + attention.  ONE WARP per (gaussian, head).
//   Online softmax accumulation, half2 HFMA2 corner gather, butterfly
//   reductions in fp32, max-free softmax.
// ---------------------------------------------------------------------------
__global__ void __launch_bounds__(256, 4) gather_attn()
{
    const int wid  = (blockIdx.x * 256 + threadIdx.x) >> 5;  // 0..65535
    const int lane = threadIdx.x & 31;
    const int g = wid >> 3;
    const int h = wid & 7;
    const int hidx2 = 2 * (h * 32 + lane);     // half2 offset within pixel record

    const uint4* __restrict__ wp = g_wh + (size_t)wid * NK;
    const int4*  __restrict__ op = g_o4 + (size_t)wid * NK;

    // Pre-load the 3 token queries (2 channels/lane), fold in HD^-0.5.
    const __half2* qg = g_qh + ((((size_t)g * 3) * ATTN + h * HDIM) >> 1) + lane;
    float2 q0 = __half22float2(qg[0]);
    float2 q1 = __half22float2(qg[ATTN / 2]);
    float2 q2 = __half22float2(qg[ATTN]);
    q0.x *= 0.125f; q0.y *= 0.125f;
    q1.x *= 0.125f; q1.y *= 0.125f;
    q2.x *= 0.125f; q2.y *= 0.125f;

    float sum0 = 0.f, sum1 = 0.f, sum2 = 0.f;
    float oa0 = 0.f, ob0 = 0.f, oa1 = 0.f, ob1 = 0.f, oa2 = 0.f, ob2 = 0.f;

    #pragma unroll
    for (int k = 0; k < NK; k++) {
        uint4 uw = wp[k];                       // warp-uniform broadcast loads
        int4  o  = op[k];
        __half2 kacc = __floats2half2_rn(0.f, 0.f);
        __half2 vacc = __floats2half2_rn(0.f, 0.f);
        {
            float2 raw = *(const float2*)(g_kvh + o.x + hidx2);
            kacc = __hfma2(*(__half2*)&uw.x, *(__half2*)&raw.x, kacc);
            vacc = __hfma2(*(__half2*)&uw.x, *(__half2*)&raw.y, vacc);
        }
        {
            float2 raw = *(const float2*)(g_kvh + o.y + hidx2);
            kacc = __hfma2(*(__half2*)&uw.y, *(__half2*)&raw.x, kacc);
            vacc = __hfma2(*(__half2*)&uw.y, *(__half2*)&raw.y, vacc);
        }
        {
            float2 raw = *(const float2*)(g_kvh + o.z + hidx2);
            kacc = __hfma2(*(__half2*)&uw.z, *(__half2*)&raw.x, kacc);
            vacc = __hfma2(*(__half2*)&uw.z, *(__half2*)&raw.y, vacc);
        }
        {
            float2 raw = *(const float2*)(g_kvh + o.w + hidx2);
            kacc = __hfma2(*(__half2*)&uw.w, *(__half2*)&raw.x, kacc);
            vacc = __hfma2(*(__half2*)&uw.w, *(__half2*)&raw.y, vacc);
        }
        float2 kf = __half22float2(kacc);
        float2 vf = __half22float2(vacc);

        // 3 independent butterflies (ILP); online exp-weighted accumulation.
        float s0 = warp_sum(q0.x * kf.x + q0.y * kf.y);
        float s1 = warp_sum(q1.x * kf.x + q1.y * kf.y);
        float s2 = warp_sum(q2.x * kf.x + q2.y * kf.y);
        float e0 = __expf(s0);                  // |s| ~ O(5): no max needed
        float e1 = __expf(s1);
        float e2 = __expf(s2);
        sum0 += e0; oa0 += e0 * vf.x; ob0 += e0 * vf.y;
        sum1 += e1; oa1 += e1 * vf.x; ob1 += e1 * vf.y;
        sum2 += e2; oa2 += e2 * vf.x; ob2 += e2 * vf.y;
    }

    const size_t obase = (((size_t)g * 3) * ATTN + h * HDIM) / 2 + lane;
    float i0 = __fdividef(1.0f, sum0);
    float i1 = __fdividef(1.0f, sum1);
    float i2 = __fdividef(1.0f, sum2);
    g_attnh[obase]            = __floats2half2_rn(oa0 * i0, ob0 * i0);
    g_attnh[obase + ATTN / 2] = __floats2half2_rn(oa1 * i1, ob1 * i1);
    g_attnh[obase + ATTN]     = __floats2half2_rn(oa2 * i2, ob2 * i2);
}

// ---------------------------------------------------------------------------
// Kernel 4: output projection + residual.
//   out[row, f] = sum_a g_attnh[row, a] * Wout[a, f] + b_out[f] + feat[row, f]
// ---------------------------------------------------------------------------
__global__ void __launch_bounds__(256) out_gemm(
    const float* __restrict__ Wout, const float* __restrict__ b_out,
    const float* __restrict__ feat, float* __restrict__ out)
{
    __shared__ float As[128][34];  // rows x kchunk (padded, even stride)
    __shared__ float Bs[32][33];   // k x col (padded)

    const int rBase = blockIdx.x * 128;
    const int tid = threadIdx.x;
    const int tx = tid & 7;        // col group (x4) -> 32 cols
    const int ty = tid >> 3;       // row group (x4) -> 128 rows

    float acc[4][4] = {};

    for (int kk = 0; kk < ATTN; kk += 32) {
        #pragma unroll
        for (int i = tid; i < 128 * 16; i += 256) {
            int r = i >> 4, kp = i & 15;
            float2 v = __half22float2(
                g_attnh[((size_t)(rBase + r) * ATTN + kk + kp * 2) >> 1]);
            *(float2*)&As[r][kp * 2] = v;
        }
        #pragma unroll
        for (int i = tid; i < 32 * 32; i += 256) {
            int k = i >> 5, c = i & 31;
            Bs[k][c] = Wout[(size_t)(kk + k) * GFD + c];
        }
        __syncthreads();
        #pragma unroll
        for (int k = 0; k < 32; k++) {
            float av[4], bv[4];
            #pragma unroll
            for (int i = 0; i < 4; i++) av[i] = As[ty * 4 + i][k];
            #pragma unroll
            for (int j = 0; j < 4; j++) bv[j] = Bs[k][tx * 4 + j];
            #pragma unroll
            for (int i = 0; i < 4; i++)
                #pragma unroll
                for (int j = 0; j < 4; j++) acc[i][j] += av[i] * bv[j];
        }
        __syncthreads();
    }
    #pragma unroll
    for (int i = 0; i < 4; i++) {
        int grow = rBase + ty * 4 + i;
        #pragma unroll
        for (int j = 0; j < 4; j++) {
            int col = tx * 4 + j;
            out[(size_t)grow * GFD + col] =
                acc[i][j] + b_out[col] + feat[(size_t)grow * GFD + col];
        }
    }
}

// ---------------------------------------------------------------------------
// Launch
// ---------------------------------------------------------------------------
extern "C" void kernel_launch(void* const* d_in, const int* in_sizes, int n_in,
                              void* d_out, int out_size)
{
    const float* means      = (const float*)d_in[0];
    const float* scales     = (const float*)d_in[1];
    const float* rotations  = (const float*)d_in[2];
    const float* features   = (const float*)d_in[3];
    const float* transforms = (const float*)d_in[4];
    const float* projection = (const float*)d_in[5];
    const float* image_feat = (const float*)d_in[6];
    const float* Wq         = (const float*)d_in[7];
    const float* Wk         = (const float*)d_in[8];
    const float* Wv         = (const float*)d_in[9];
    const float* W_off      = (const float*)d_in[10];
    const float* b_off      = (const float*)d_in[11];
    const float* Wout       = (const float*)d_in[12];
    const float* b_out      = (const float*)d_in[13];
    float* out = (float*)d_out;

    // 0) fp32 -> fp16 operand conversion
    convert_fp16<<<(N_CONV + 255) / 256, 256>>>(Wk, Wv, image_feat, features, Wq);
    // 1) KV feature maps: tensor-core GEMM, fp16-interleaved pixel-major output
    kv_gemm_wmma<<<dim3(NPIX / 64, 1024 / 128), 256>>>();
    // 2) Q projection: tensor-core GEMM, fp16 output
    q_gemm_wmma<<<dim3(ATTN / 64, NROW / 128), 256>>>();
    // 3a) offsets -> resolved bilinear weights (half2) + corner offsets
    coord_kernel<<<NG, 256>>>(means, scales, rotations, transforms,
                              projection, W_off, b_off);
    // 3b) barrier-free gather + attention, online softmax (one warp per (g,h))
    gather_attn<<<NG, 256>>>();
    // 4) output projection + bias + residual
    out_gemm<<<NROW / 128, 256>>>(Wout, b_out, features, out);
}

// round 16
// speedup vs baseline: 1.2748x; 1.2748x over previous
#include <cuda_runtime.h>
#include <cuda_fp16.h>
#include <mma.h>
#include <math.h>

// ---------------------------------------------------------------------------
// Problem constants
//   G=8192 gaussians, BS=1, 3 tokens, GFD=32, ATTN=512, H=8 heads, HD=64
//   image_features [256,64,64], K = 12 sample points (6 fixed + 6 learned)
// ---------------------------------------------------------------------------
#define NG      8192
#define NROW    (NG*3)        // 24576 (gaussian,token) rows
#define ATTN    512
#define GFD     32
#define NHEAD   8
#define HDIM    64
#define IMGW    64
#define IMGH    64
#define NPIX    (IMGW*IMGH)   // 4096
#define CIMG    256
#define NK      12

using namespace nvcuda;

// Scratch (static device globals: allocation-free per harness rules)
// g_kvh layout: per pixel, 256 channel-pairs; slot 2p = K half2 (ch 2p,2p+1),
//               slot 2p+1 = V half2.  One 8-byte load fetches K+V for a lane.
__device__ __half2 g_kvh[NPIX * 512];        // 8 MB, L2-resident
__device__ __half2 g_qh[NROW * ATTN / 2];    // q_full, fp16               (25 MB)
__device__ __half2 g_attnh[NROW * ATTN / 2]; // attention output, fp16     (25 MB)
__device__ uint4   g_wh[NG * NHEAD * NK];    // 4 corner weights, each replicated half2
__device__ int4    g_o4[NG * NHEAD * NK];    // clamped corner offsets (x512)

// fp16 operand buffers for the tensor-core KV GEMM
__device__ __align__(128) __half g_kvw16[1024 * CIMG];   // Wk;Wv rows [a][k]
__device__ __align__(128) __half g_img16[CIMG * NPIX];   // [k][pix]

__constant__ float c_fix[6][3] = {
    {0.f,0.f,0.f},{1.f,0.f,0.f},{0.f,1.f,0.f},
    {0.f,0.f,1.f},{-1.f,0.f,0.f},{0.f,-1.f,0.f}};

__device__ __forceinline__ float sigm_clamped(float x) {
    x = fminf(fmaxf(x, -9.21f), 9.21f);
    return 1.0f / (1.0f + __expf(-x));
}

// 5-stage butterfly warp sum (redux.sync.f32 not available on sm_103 target)
__device__ __forceinline__ float warp_sum(float v) {
    #pragma unroll
    for (int o = 16; o > 0; o >>= 1) v += __shfl_xor_sync(0xffffffffu, v, o);
    return v;
}

// ---------------------------------------------------------------------------
// Kernel 0: fp32 -> fp16 conversion for KV-GEMM operands only.
// ---------------------------------------------------------------------------
#define N_WKV   (1024 * CIMG)           // 262144
#define N_IMG   (CIMG * NPIX)           // 1048576
#define N_CONV  (N_WKV + N_IMG)

__global__ void __launch_bounds__(256) convert_fp16(
    const float* __restrict__ Wk, const float* __restrict__ Wv,
    const float* __restrict__ img)
{
    int i = blockIdx.x * 256 + threadIdx.x;
    if (i >= N_CONV) return;
    if (i < N_WKV / 2) {
        g_kvw16[i] = __float2half_rn(Wk[i]);
    } else if (i < N_WKV) {
        g_kvw16[i] = __float2half_rn(Wv[i - N_WKV / 2]);
    } else {
        int j = i - N_WKV;
        g_img16[j] = __float2half_rn(img[j]);
    }
}

// ---------------------------------------------------------------------------
// Kernel 1: KV maps via tensor cores, SMEM-STAGED (v2).
//   C[a,pix] = sum_k Wkv16[a,k] * img16[k,pix]
//   Block tile 64(a) x 128(pix), K-steps of 32 staged through padded smem.
//   Warp grid 2(a) x 4(pix): warp tile 32x32 = 2x2 m16n16k16 fragments.
//   Epilogue via float smem -> half2 pack, K/V-interleaved (validated in R15).
// ---------------------------------------------------------------------------
__global__ void __launch_bounds__(256) kv_gemm_wmma()
{
    __shared__ __align__(16) __half sA[64][40];    // a x k   (pad 32->40)
    __shared__ __align__(16) __half sB[32][136];   // k x pix (pad 128->136)
    __shared__ __align__(16) float  sC[64][128];

    const int tid  = threadIdx.x;
    const int warp = tid >> 5;
    const int wa = warp & 1;        // a group (x32)
    const int wp = warp >> 1;       // pix group (x32)
    const int aBase = blockIdx.y * 64;
    const int pBase = blockIdx.x * 128;

    wmma::fragment<wmma::accumulator, 16, 16, 16, float> c[2][2];
    #pragma unroll
    for (int i = 0; i < 2; i++)
        #pragma unroll
        for (int j = 0; j < 2; j++) wmma::fill_fragment(c[i][j], 0.0f);

    for (int k0 = 0; k0 < CIMG; k0 += 32) {
        // A tile: 64 rows x 32 k (16 half2/row), coalesced
        #pragma unroll
        for (int i = tid; i < 64 * 16; i += 256) {
            int r = i >> 4, cp = i & 15;
            *(__half2*)&sA[r][cp * 2] =
                *(const __half2*)&g_kvw16[(size_t)(aBase + r) * CIMG + k0 + cp * 2];
        }
        // B tile: 32 k-rows x 128 pix (64 half2/row), coalesced
        #pragma unroll
        for (int i = tid; i < 32 * 64; i += 256) {
            int r = i >> 6, cp = i & 63;
            *(__half2*)&sB[r][cp * 2] =
                *(const __half2*)&g_img16[(size_t)(k0 + r) * NPIX + pBase + cp * 2];
        }
        __syncthreads();
        #pragma unroll
        for (int kk = 0; kk < 2; kk++) {
            wmma::fragment<wmma::matrix_a, 16, 16, 16, __half, wmma::row_major> af[2];
            wmma::fragment<wmma::matrix_b, 16, 16, 16, __half, wmma::row_major> bf[2];
            #pragma unroll
            for (int i = 0; i < 2; i++)
                wmma::load_matrix_sync(af[i], &sA[wa * 32 + i * 16][kk * 16], 40);
            #pragma unroll
            for (int j = 0; j < 2; j++)
                wmma::load_matrix_sync(bf[j], &sB[kk * 16][wp * 32 + j * 16], 136);
            #pragma unroll
            for (int i = 0; i < 2; i++)
                #pragma unroll
                for (int j = 0; j < 2; j++)
                    wmma::mma_sync(c[i][j], af[i], bf[j], c[i][j]);
        }
        __syncthreads();
    }

    #pragma unroll
    for (int i = 0; i < 2; i++)
        #pragma unroll
        for (int j = 0; j < 2; j++)
            wmma::store_matrix_sync(&sC[wa * 32 + i * 16][wp * 32 + j * 16],
                                    c[i][j], 128, wmma::mem_row_major);
    __syncthreads();

    // Pack: 32 channel-pairs x 128 pixels, K/V interleave into g_kvh.
    const bool isK = (aBase < 512);
    const int paBase = aBase >> 1;
    for (int idx = tid; idx < 32 * 128; idx += 256) {
        int pal = idx >> 7, pl = idx & 127;
        float lo = sC[2 * pal][pl];
        float hi = sC[2 * pal + 1][pl];
        int pa = paBase + pal;
        int slot = isK ? (2 * pa) : (2 * (pa - 256) + 1);
        g_kvh[(size_t)(pBase + pl) * 512 + slot] = __floats2half2_rn(lo, hi);
    }
}

// ---------------------------------------------------------------------------
// Kernel 2: Q projection (scalar, fp16 output) — R14 version.
//   g_qh[row, a] = sum_f feat[row, f] * Wq[f, a]
// ---------------------------------------------------------------------------
__global__ void __launch_bounds__(256) q_gemm(
    const float* __restrict__ feat, const float* __restrict__ Wq)
{
    __shared__ float As[64][33];   // rows x k
    __shared__ float Bs[32][64];   // k x cols

    const int rBase = blockIdx.y * 64;
    const int cBase = blockIdx.x * 64;
    const int tid = threadIdx.x;
    const int tx = tid & 15, ty = tid >> 4;

    #pragma unroll
    for (int i = tid; i < 64 * 32; i += 256) {
        int r = i >> 5, k = i & 31;
        As[r][k] = feat[(size_t)(rBase + r) * 32 + k];
    }
    #pragma unroll
    for (int i = tid; i < 32 * 64; i += 256) {
        int k = i >> 6, c = i & 63;
        Bs[k][c] = Wq[(size_t)k * ATTN + cBase + c];
    }
    __syncthreads();

    float acc[4][4] = {};
    #pragma unroll
    for (int k = 0; k < 32; k++) {
        float av[4], bv[4];
        #pragma unroll
        for (int i = 0; i < 4; i++) av[i] = As[ty * 4 + i][k];
        #pragma unroll
        for (int j = 0; j < 4; j++) bv[j] = Bs[k][tx * 4 + j];
        #pragma unroll
        for (int i = 0; i < 4; i++)
            #pragma unroll
            for (int j = 0; j < 4; j++) acc[i][j] += av[i] * bv[j];
    }
    // pack 4 halves per 8-byte store (index is even: cBase%64==0, tx*4 even)
    #pragma unroll
    for (int i = 0; i < 4; i++) {
        __half2 p0 = __floats2half2_rn(acc[i][0], acc[i][1]);
        __half2 p1 = __floats2half2_rn(acc[i][2], acc[i][3]);
        float2 st;
        *(__half2*)&st.x = p0;
        *(__half2*)&st.y = p1;
        *(float2*)(g_qh + (((size_t)(rBase + ty * 4 + i) * ATTN + cBase + tx * 4) >> 1)) = st;
    }
}

// ---------------------------------------------------------------------------
// Kernel 3a: coordinate precompute, 4 GAUSSIANS PER BLOCK (amortize the
//   W_off smem fill 4x).  One warp per head within each gaussian iteration.
// ---------------------------------------------------------------------------
__global__ void __launch_bounds__(256) coord_kernel(
    const float* __restrict__ means, const float* __restrict__ scales,
    const float* __restrict__ rots, const float* __restrict__ transforms,
    const float* __restrict__ proj, const float* __restrict__ W_off,
    const float* __restrict__ b_off)
{
    const int tid = threadIdx.x;
    const int h = tid >> 5;
    const int lane = tid & 31;

    __shared__ float sqm[NHEAD][HDIM];   // per-head token-mean query (warp-private use)
    __shared__ float slog[NHEAD][18];    // offset logits (warp-private use)
    __shared__ float sW[67 * 18];
    __shared__ float sb[18];
    __shared__ float sP[12];
    __shared__ float sMisc[16];          // 0-2 mean_w, 3-11 R(row major), 12-14 scales

    for (int i = tid; i < 67 * 18; i += 256) sW[i] = W_off[i];
    if (tid < 18) sb[tid] = b_off[tid];
    if (tid >= 32 && tid < 44) sP[tid - 32] = proj[tid - 32];

    for (int gi = 0; gi < 4; gi++) {
        const int g = blockIdx.x * 4 + gi;
        __syncthreads();   // sW ready (first iter); sMisc free for overwrite (later iters)

        if (tid == 64) {
            float mx = means[g * 3], my = means[g * 3 + 1], mz = means[g * 3 + 2];
            const float* T = transforms + (size_t)g * 16;
            sMisc[0] = T[0] * mx + T[1] * my + T[2]  * mz + T[3];
            sMisc[1] = T[4] * mx + T[5] * my + T[6]  * mz + T[7];
            sMisc[2] = T[8] * mx + T[9] * my + T[10] * mz + T[11];
            float qw = rots[g * 4], qx = rots[g * 4 + 1], qy = rots[g * 4 + 2], qz = rots[g * 4 + 3];
            float inv = rsqrtf(qw * qw + qx * qx + qy * qy + qz * qz);
            qw *= inv; qx *= inv; qy *= inv; qz *= inv;
            sMisc[3]  = 1.f - 2.f * (qy * qy + qz * qz);
            sMisc[4]  = 2.f * (qx * qy - qw * qz);
            sMisc[5]  = 2.f * (qx * qz + qw * qy);
            sMisc[6]  = 2.f * (qx * qy + qw * qz);
            sMisc[7]  = 1.f - 2.f * (qx * qx + qz * qz);
            sMisc[8]  = 2.f * (qy * qz - qw * qx);
            sMisc[9]  = 2.f * (qx * qz - qw * qy);
            sMisc[10] = 2.f * (qy * qz + qw * qx);
            sMisc[11] = 1.f - 2.f * (qx * qx + qy * qy);
            sMisc[12] = scales[g * 3]; sMisc[13] = scales[g * 3 + 1]; sMisc[14] = scales[g * 3 + 2];
        }

        // per-head token-mean query (warp-private region of sqm)
        {
            const __half2* qg = g_qh + ((((size_t)g * 3) * ATTN + h * HDIM) >> 1) + lane;
            float2 q0 = __half22float2(qg[0]);
            float2 q1 = __half22float2(qg[ATTN / 2]);
            float2 q2 = __half22float2(qg[ATTN]);
            sqm[h][lane * 2]     = (q0.x + q1.x + q2.x) * (1.0f / 3.0f);
            sqm[h][lane * 2 + 1] = (q0.y + q1.y + q2.y) * (1.0f / 3.0f);
        }
        __syncthreads();   // sMisc visible to all warps

        // offset logits: off_in = [mean_w(3), q_mean(64)] @ W_off + b_off
        if (lane < 18) {
            float acc = sb[lane] + sMisc[0] * sW[lane] + sMisc[1] * sW[18 + lane] + sMisc[2] * sW[36 + lane];
            #pragma unroll 8
            for (int c = 0; c < HDIM; c++) acc += sqm[h][c] * sW[(3 + c) * 18 + lane];
            slog[h][lane] = acc;
        }
        __syncwarp();

        if (lane < NK) {
            const int k = lane;
            float s0, s1, s2;
            if (k < 6) {
                s0 = c_fix[k][0]; s1 = c_fix[k][1]; s2 = c_fix[k][2];
            } else {
                int b = (k - 6) * 3;
                s0 = sigm_clamped(slog[h][b])     - 0.5f;
                s1 = sigm_clamped(slog[h][b + 1]) - 0.5f;
                s2 = sigm_clamped(slog[h][b + 2]) - 0.5f;
            }
            float o0 = s0 * sMisc[12], o1 = s1 * sMisc[13], o2 = s2 * sMisc[14];
            // world offset = R^T @ o + mean_w
            float wx = sMisc[3] * o0 + sMisc[6] * o1 + sMisc[9]  * o2 + sMisc[0];
            float wy = sMisc[4] * o0 + sMisc[7] * o1 + sMisc[10] * o2 + sMisc[1];
            float wz = sMisc[5] * o0 + sMisc[8] * o1 + sMisc[11] * o2 + sMisc[2];
            float p0 = sP[0] * wx + sP[1] * wy + sP[2]  * wz + sP[3];
            float p1 = sP[4] * wx + sP[5] * wy + sP[6]  * wz + sP[7];
            float p2 = sP[8] * wx + sP[9] * wy + sP[10] * wz + sP[11];
            float z = fmaxf(p2, 1e-5f);
            float xn = fminf(fmaxf(p0 / z * (1.0f / IMGW), 0.0f), 0.9999f);
            float yn = fminf(fmaxf(p1 / z * (1.0f / IMGH), 0.0f), 0.9999f);
            float x = xn * (float)IMGW - 0.5f;
            float y = yn * (float)IMGH - 0.5f;

            // Resolve bilinear sampling: weights (zeroed when OOB, replicated
            // half2) + clamped corner offsets in units of half2 (pixel * 512).
            float xf = floorf(x), yf = floorf(y);
            int x0 = (int)xf, y0 = (int)yf;
            float fx = x - xf, fy = y - yf;
            float w00 = (1.f - fx) * (1.f - fy), w10 = fx * (1.f - fy);
            float w01 = (1.f - fx) * fy,         w11 = fx * fy;
            int x1 = x0 + 1, y1 = y0 + 1;
            float vx0 = (x0 >= 0) ? 1.f : 0.f;
            float vx1 = (x1 <= IMGW - 1) ? 1.f : 0.f;
            float vy0 = (y0 >= 0) ? 1.f : 0.f;
            float vy1 = (y1 <= IMGH - 1) ? 1.f : 0.f;
            int cx0 = max(x0, 0), cx1 = min(x1, IMGW - 1);
            int cy0 = max(y0, 0), cy1 = min(y1, IMGH - 1);

            size_t idx = ((size_t)g * NHEAD + h) * NK + k;
            __half2 h00 = __float2half2_rn(w00 * vx0 * vy0);
            __half2 h10 = __float2half2_rn(w10 * vx1 * vy0);
            __half2 h01 = __float2half2_rn(w01 * vx0 * vy1);
            __half2 h11 = __float2half2_rn(w11 * vx1 * vy1);
            uint4 uw;
            uw.x = *(unsigned*)&h00;
            uw.y = *(unsigned*)&h10;
            uw.z = *(unsigned*)&h01;
            uw.w = *(unsigned*)&h11;
            g_wh[idx] = uw;
            int4 o4;
            o4.x = (cy0 * IMGW + cx0) * 512;
            o4.y = (cy0 * IMGW + cx1) * 512;
            o4.z = (cy1 * IMGW + cx0) * 512;
            o4.w = (cy1 * IMGW + cx1) * 512;
            g_o4[idx] = o4;
        }
    }
}

// ---------------------------------------------------------------------------
// Kernel 3b: gather + attention.  ONE WARP per (gaussian, head).
//   Online softmax accumulation, half2 HFMA2 corner gather, butterfly
//   reductions in fp32, max-free softmax.
// ---------------------------------------------------------------------------
__global__ void __launch_bounds__(256, 4) gather_attn()
{
    const int wid  = (blockIdx.x * 256 + threadIdx.x) >> 5;  // 0..65535
    const int lane = threadIdx.x & 31;
    const int g = wid >> 3;
    const int h = wid & 7;
    const int hidx2 = 2 * (h * 32 + lane);     // half2 offset within pixel record

    const uint4* __restrict__ wp = g_wh + (size_t)wid * NK;
    const int4*  __restrict__ op = g_o4 + (size_t)wid * NK;

    // Pre-load the 3 token queries (2 channels/lane), fold in HD^-0.5.
    const __half2* qg = g_qh + ((((size_t)g * 3) * ATTN + h * HDIM) >> 1) + lane;
    float2 q0 = __half22float2(qg[0]);
    float2 q1 = __half22float2(qg[ATTN / 2]);
    float2 q2 = __half22float2(qg[ATTN]);
    q0.x *= 0.125f; q0.y *= 0.125f;
    q1.x *= 0.125f; q1.y *= 0.125f;
    q2.x *= 0.125f; q2.y *= 0.125f;

    float sum0 = 0.f, sum1 = 0.f, sum2 = 0.f;
    float oa0 = 0.f, ob0 = 0.f, oa1 = 0.f, ob1 = 0.f, oa2 = 0.f, ob2 = 0.f;

    #pragma unroll
    for (int k = 0; k < NK; k++) {
        uint4 uw = wp[k];                       // warp-uniform broadcast loads
        int4  o  = op[k];
        __half2 kacc = __floats2half2_rn(0.f, 0.f);
        __half2 vacc = __floats2half2_rn(0.f, 0.f);
        {
            float2 raw = *(const float2*)(g_kvh + o.x + hidx2);
            kacc = __hfma2(*(__half2*)&uw.x, *(__half2*)&raw.x, kacc);
            vacc = __hfma2(*(__half2*)&uw.x, *(__half2*)&raw.y, vacc);
        }
        {
            float2 raw = *(const float2*)(g_kvh + o.y + hidx2);
            kacc = __hfma2(*(__half2*)&uw.y, *(__half2*)&raw.x, kacc);
            vacc = __hfma2(*(__half2*)&uw.y, *(__half2*)&raw.y, vacc);
        }
        {
            float2 raw = *(const float2*)(g_kvh + o.z + hidx2);
            kacc = __hfma2(*(__half2*)&uw.z, *(__half2*)&raw.x, kacc);
            vacc = __hfma2(*(__half2*)&uw.z, *(__half2*)&raw.y, vacc);
        }
        {
            float2 raw = *(const float2*)(g_kvh + o.w + hidx2);
            kacc = __hfma2(*(__half2*)&uw.w, *(__half2*)&raw.x, kacc);
            vacc = __hfma2(*(__half2*)&uw.w, *(__half2*)&raw.y, vacc);
        }
        float2 kf = __half22float2(kacc);
        float2 vf = __half22float2(vacc);

        // 3 independent butterflies (ILP); online exp-weighted accumulation.
        float s0 = warp_sum(q0.x * kf.x + q0.y * kf.y);
        float s1 = warp_sum(q1.x * kf.x + q1.y * kf.y);
        float s2 = warp_sum(q2.x * kf.x + q2.y * kf.y);
        float e0 = __expf(s0);                  // |s| ~ O(5): no max needed
        float e1 = __expf(s1);
        float e2 = __expf(s2);
        sum0 += e0; oa0 += e0 * vf.x; ob0 += e0 * vf.y;
        sum1 += e1; oa1 += e1 * vf.x; ob1 += e1 * vf.y;
        sum2 += e2; oa2 += e2 * vf.x; ob2 += e2 * vf.y;
    }

    const size_t obase = (((size_t)g * 3) * ATTN + h * HDIM) / 2 + lane;
    float i0 = __fdividef(1.0f, sum0);
    float i1 = __fdividef(1.0f, sum1);
    float i2 = __fdividef(1.0f, sum2);
    g_attnh[obase]            = __floats2half2_rn(oa0 * i0, ob0 * i0);
    g_attnh[obase + ATTN / 2] = __floats2half2_rn(oa1 * i1, ob1 * i1);
    g_attnh[obase + ATTN]     = __floats2half2_rn(oa2 * i2, ob2 * i2);
}

// ---------------------------------------------------------------------------
// Kernel 4: output projection + residual — R14 version.
//   out[row, f] = sum_a g_attnh[row, a] * Wout[a, f] + b_out[f] + feat[row, f]
// ---------------------------------------------------------------------------
__global__ void __launch_bounds__(256) out_gemm(
    const float* __restrict__ Wout, const float* __restrict__ b_out,
    const float* __restrict__ feat, float* __restrict__ out)
{
    __shared__ float As[128][34];  // rows x kchunk (padded, even stride)
    __shared__ float Bs[32][33];   // k x col (padded)

    const int rBase = blockIdx.x * 128;
    const int tid = threadIdx.x;
    const int tx = tid & 7;        // col group (x4) -> 32 cols
    const int ty = tid >> 3;       // row group (x4) -> 128 rows

    float acc[4][4] = {};

    for (int kk = 0; kk < ATTN; kk += 32) {
        #pragma unroll
        for (int i = tid; i < 128 * 16; i += 256) {
            int r = i >> 4, kp = i & 15;
            float2 v = __half22float2(
                g_attnh[((size_t)(rBase + r) * ATTN + kk + kp * 2) >> 1]);
            *(float2*)&As[r][kp * 2] = v;
        }
        #pragma unroll
        for (int i = tid; i < 32 * 32; i += 256) {
            int k = i >> 5, c = i & 31;
            Bs[k][c] = Wout[(size_t)(kk + k) * GFD + c];
        }
        __syncthreads();
        #pragma unroll
        for (int k = 0; k < 32; k++) {
            float av[4], bv[4];
            #pragma unroll
            for (int i = 0; i < 4; i++) av[i] = As[ty * 4 + i][k];
            #pragma unroll
            for (int j = 0; j < 4; j++) bv[j] = Bs[k][tx * 4 + j];
            #pragma unroll
            for (int i = 0; i < 4; i++)
                #pragma unroll
                for (int j = 0; j < 4; j++) acc[i][j] += av[i] * bv[j];
        }
        __syncthreads();
    }
    #pragma unroll
    for (int i = 0; i < 4; i++) {
        int grow = rBase + ty * 4 + i;
        #pragma unroll
        for (int j = 0; j < 4; j++) {
            int col = tx * 4 + j;
            out[(size_t)grow * GFD + col] =
                acc[i][j] + b_out[col] + feat[(size_t)grow * GFD + col];
        }
    }
}

// ---------------------------------------------------------------------------
// Launch
// ---------------------------------------------------------------------------
extern "C" void kernel_launch(void* const* d_in, const int* in_sizes, int n_in,
                              void* d_out, int out_size)
{
    const float* means      = (const float*)d_in[0];
    const float* scales     = (const float*)d_in[1];
    const float* rotations  = (const float*)d_in[2];
    const float* features   = (const float*)d_in[3];
    const float* transforms = (const float*)d_in[4];
    const float* projection = (const float*)d_in[5];
    const float* image_feat = (const float*)d_in[6];
    const float* Wq         = (const float*)d_in[7];
    const float* Wk         = (const float*)d_in[8];
    const float* Wv         = (const float*)d_in[9];
    const float* W_off      = (const float*)d_in[10];
    const float* b_off      = (const float*)d_in[11];
    const float* Wout       = (const float*)d_in[12];
    const float* b_out      = (const float*)d_in[13];
    float* out = (float*)d_out;

    // 0) fp32 -> fp16 conversion for KV-GEMM operands
    convert_fp16<<<(N_CONV + 255) / 256, 256>>>(Wk, Wv, image_feat);
    // 1) KV feature maps: smem-staged tensor-core GEMM
    kv_gemm_wmma<<<dim3(NPIX / 128, 1024 / 64), 256>>>();
    // 2) Q projection: scalar GEMM, fp16 output
    q_gemm<<<dim3(ATTN / 64, NROW / 64), 256>>>(features, Wq);
    // 3a) offsets -> resolved bilinear weights (half2) + corner offsets, 4 g/block
    coord_kernel<<<NG / 4, 256>>>(means, scales, rotations, transforms,
                                  projection, W_off, b_off);
    // 3b) barrier-free gather + attention, online softmax (one warp per (g,h))
    gather_attn<<<NG, 256>>>();
    // 4) output projection + bias + residual
    out_gemm<<<NROW / 128, 256>>>(Wout, b_out, features, out);
}

// round 17
// speedup vs baseline: 1.4015x; 1.0994x over previous
#include <cuda_runtime.h>
#include <cuda_fp16.h>
#include <mma.h>
#include <math.h>

// ---------------------------------------------------------------------------
// Problem constants
//   G=8192 gaussians, BS=1, 3 tokens, GFD=32, ATTN=512, H=8 heads, HD=64
//   image_features [256,64,64], K = 12 sample points (6 fixed + 6 learned)
// ---------------------------------------------------------------------------
#define NG      8192
#define NROW    (NG*3)        // 24576 (gaussian,token) rows
#define ATTN    512
#define GFD     32
#define NHEAD   8
#define HDIM    64
#define IMGW    64
#define IMGH    64
#define NPIX    (IMGW*IMGH)   // 4096
#define CIMG    256
#define NK      12

using namespace nvcuda;

// Scratch (static device globals: allocation-free per harness rules)
// g_kvh layout: per pixel, 256 channel-pairs; slot 2p = K half2 (ch 2p,2p+1),
//               slot 2p+1 = V half2.  One 8-byte load fetches K+V for a lane.
__device__ __half2 g_kvh[NPIX * 512];        // 8 MB, L2-resident
__device__ __half2 g_qh[NROW * ATTN / 2];    // q_full, fp16               (25 MB)
__device__ __half2 g_attnh[NROW * ATTN / 2]; // attention output, fp16     (25 MB)
__device__ uint4   g_wh[NG * NHEAD * NK];    // 4 corner weights, each replicated half2
__device__ int4    g_o4[NG * NHEAD * NK];    // clamped corner offsets (x512)

// fp16 operand buffers for tensor-core GEMMs
__device__ __align__(128) __half g_kvw16[1024 * CIMG];   // Wk;Wv rows [a][k]
__device__ __align__(128) __half g_img16[CIMG * NPIX];   // [k][pix]
__device__ __align__(128) __half g_feat16[NROW * GFD];   // [row][f]
__device__ __align__(128) __half g_wq16[GFD * ATTN];     // [f][a]
__device__ __align__(128) __half g_wout16[ATTN * GFD];   // [a][f]

__constant__ float c_fix[6][3] = {
    {0.f,0.f,0.f},{1.f,0.f,0.f},{0.f,1.f,0.f},
    {0.f,0.f,1.f},{-1.f,0.f,0.f},{0.f,-1.f,0.f}};

__device__ __forceinline__ float sigm_clamped(float x) {
    x = fminf(fmaxf(x, -9.21f), 9.21f);
    return 1.0f / (1.0f + __expf(-x));
}

// 5-stage butterfly warp sum (redux.sync.f32 not available on sm_103 target)
__device__ __forceinline__ float warp_sum(float v) {
    #pragma unroll
    for (int o = 16; o > 0; o >>= 1) v += __shfl_xor_sync(0xffffffffu, v, o);
    return v;
}

// ---------------------------------------------------------------------------
// Kernel 0: fp32 -> fp16 conversion for all GEMM operands.
// ---------------------------------------------------------------------------
#define N_WKV   (1024 * CIMG)           // 262144
#define N_IMG   (CIMG * NPIX)           // 1048576
#define N_FEAT  (NROW * GFD)            // 786432
#define N_WQ    (GFD * ATTN)            // 16384
#define N_WOUT  (ATTN * GFD)            // 16384
#define N_CONV  (N_WKV + N_IMG + N_FEAT + N_WQ + N_WOUT)

__global__ void __launch_bounds__(256) convert_fp16(
    const float* __restrict__ Wk, const float* __restrict__ Wv,
    const float* __restrict__ img, const float* __restrict__ feat,
    const float* __restrict__ Wq, const float* __restrict__ Wout)
{
    int i = blockIdx.x * 256 + threadIdx.x;
    if (i >= N_CONV) return;
    if (i < N_WKV / 2) {
        g_kvw16[i] = __float2half_rn(Wk[i]);
    } else if (i < N_WKV) {
        g_kvw16[i] = __float2half_rn(Wv[i - N_WKV / 2]);
    } else if (i < N_WKV + N_IMG) {
        int j = i - N_WKV;
        g_img16[j] = __float2half_rn(img[j]);
    } else if (i < N_WKV + N_IMG + N_FEAT) {
        int j = i - N_WKV - N_IMG;
        g_feat16[j] = __float2half_rn(feat[j]);
    } else if (i < N_WKV + N_IMG + N_FEAT + N_WQ) {
        int j = i - N_WKV - N_IMG - N_FEAT;
        g_wq16[j] = __float2half_rn(Wq[j]);
    } else {
        int j = i - N_WKV - N_IMG - N_FEAT - N_WQ;
        g_wout16[j] = __float2half_rn(Wout[j]);
    }
}

// ---------------------------------------------------------------------------
// Kernel 1: KV maps via tensor cores, smem-staged (validated in R16).
//   C[a,pix] = sum_k Wkv16[a,k] * img16[k,pix]
//   Block tile 64(a) x 128(pix), warp grid 2x4, 2x2 m16n16k16 frags/warp.
// ---------------------------------------------------------------------------
__global__ void __launch_bounds__(256) kv_gemm_wmma()
{
    __shared__ __align__(16) __half sA[64][40];    // a x k   (pad 32->40)
    __shared__ __align__(16) __half sB[32][136];   // k x pix (pad 128->136)
    __shared__ __align__(16) float  sC[64][128];

    const int tid  = threadIdx.x;
    const int warp = tid >> 5;
    const int wa = warp & 1;        // a group (x32)
    const int wp = warp >> 1;       // pix group (x32)
    const int aBase = blockIdx.y * 64;
    const int pBase = blockIdx.x * 128;

    wmma::fragment<wmma::accumulator, 16, 16, 16, float> c[2][2];
    #pragma unroll
    for (int i = 0; i < 2; i++)
        #pragma unroll
        for (int j = 0; j < 2; j++) wmma::fill_fragment(c[i][j], 0.0f);

    for (int k0 = 0; k0 < CIMG; k0 += 32) {
        #pragma unroll
        for (int i = tid; i < 64 * 16; i += 256) {
            int r = i >> 4, cp = i & 15;
            *(__half2*)&sA[r][cp * 2] =
                *(const __half2*)&g_kvw16[(size_t)(aBase + r) * CIMG + k0 + cp * 2];
        }
        #pragma unroll
        for (int i = tid; i < 32 * 64; i += 256) {
            int r = i >> 6, cp = i & 63;
            *(__half2*)&sB[r][cp * 2] =
                *(const __half2*)&g_img16[(size_t)(k0 + r) * NPIX + pBase + cp * 2];
        }
        __syncthreads();
        #pragma unroll
        for (int kk = 0; kk < 2; kk++) {
            wmma::fragment<wmma::matrix_a, 16, 16, 16, __half, wmma::row_major> af[2];
            wmma::fragment<wmma::matrix_b, 16, 16, 16, __half, wmma::row_major> bf[2];
            #pragma unroll
            for (int i = 0; i < 2; i++)
                wmma::load_matrix_sync(af[i], &sA[wa * 32 + i * 16][kk * 16], 40);
            #pragma unroll
            for (int j = 0; j < 2; j++)
                wmma::load_matrix_sync(bf[j], &sB[kk * 16][wp * 32 + j * 16], 136);
            #pragma unroll
            for (int i = 0; i < 2; i++)
                #pragma unroll
                for (int j = 0; j < 2; j++)
                    wmma::mma_sync(c[i][j], af[i], bf[j], c[i][j]);
        }
        __syncthreads();
    }

    #pragma unroll
    for (int i = 0; i < 2; i++)
        #pragma unroll
        for (int j = 0; j < 2; j++)
            wmma::store_matrix_sync(&sC[wa * 32 + i * 16][wp * 32 + j * 16],
                                    c[i][j], 128, wmma::mem_row_major);
    __syncthreads();

    const bool isK = (aBase < 512);
    const int paBase = aBase >> 1;
    for (int idx = tid; idx < 32 * 128; idx += 256) {
        int pal = idx >> 7, pl = idx & 127;
        float lo = sC[2 * pal][pl];
        float hi = sC[2 * pal + 1][pl];
        int pa = paBase + pal;
        int slot = isK ? (2 * pa) : (2 * (pa - 256) + 1);
        g_kvh[(size_t)(pBase + pl) * 512 + slot] = __floats2half2_rn(lo, hi);
    }
}

// ---------------------------------------------------------------------------
// Kernel 2: Q projection via tensor cores, smem-staged.
//   g_qh[row,a] = sum_f feat16[row,f] * Wq16[f,a].  M=24576, K=32, N=512.
//   Block tile 64(rows) x 128(cols), warp grid 2x4.
// ---------------------------------------------------------------------------
__global__ void __launch_bounds__(256) q_gemm_wmma()
{
    __shared__ __align__(16) __half sA[64][40];    // rows x k (32 pad40)
    __shared__ __align__(16) __half sB[32][136];   // k x cols (128 pad136)
    __shared__ __align__(16) float  sC[64][128];

    const int tid  = threadIdx.x;
    const int warp = tid >> 5;
    const int wa = warp & 1;        // row group (x32)
    const int wp = warp >> 1;       // col group (x32)
    const int rBase = blockIdx.y * 64;
    const int cBase = blockIdx.x * 128;

    wmma::fragment<wmma::accumulator, 16, 16, 16, float> c[2][2];
    #pragma unroll
    for (int i = 0; i < 2; i++)
        #pragma unroll
        for (int j = 0; j < 2; j++) wmma::fill_fragment(c[i][j], 0.0f);

    // Single K chunk (GFD=32)
    #pragma unroll
    for (int i = tid; i < 64 * 16; i += 256) {
        int r = i >> 4, cp = i & 15;
        *(__half2*)&sA[r][cp * 2] =
            *(const __half2*)&g_feat16[(size_t)(rBase + r) * GFD + cp * 2];
    }
    #pragma unroll
    for (int i = tid; i < 32 * 64; i += 256) {
        int r = i >> 6, cp = i & 63;
        *(__half2*)&sB[r][cp * 2] =
            *(const __half2*)&g_wq16[(size_t)r * ATTN + cBase + cp * 2];
    }
    __syncthreads();
    #pragma unroll
    for (int kk = 0; kk < 2; kk++) {
        wmma::fragment<wmma::matrix_a, 16, 16, 16, __half, wmma::row_major> af[2];
        wmma::fragment<wmma::matrix_b, 16, 16, 16, __half, wmma::row_major> bf[2];
        #pragma unroll
        for (int i = 0; i < 2; i++)
            wmma::load_matrix_sync(af[i], &sA[wa * 32 + i * 16][kk * 16], 40);
        #pragma unroll
        for (int j = 0; j < 2; j++)
            wmma::load_matrix_sync(bf[j], &sB[kk * 16][wp * 32 + j * 16], 136);
        #pragma unroll
        for (int i = 0; i < 2; i++)
            #pragma unroll
            for (int j = 0; j < 2; j++)
                wmma::mma_sync(c[i][j], af[i], bf[j], c[i][j]);
    }

    #pragma unroll
    for (int i = 0; i < 2; i++)
        #pragma unroll
        for (int j = 0; j < 2; j++)
            wmma::store_matrix_sync(&sC[wa * 32 + i * 16][wp * 32 + j * 16],
                                    c[i][j], 128, wmma::mem_row_major);
    __syncthreads();

    for (int idx = tid; idx < 64 * 64; idx += 256) {
        int r = idx >> 6, cp = idx & 63;
        g_qh[((size_t)(rBase + r) * ATTN + cBase + 2 * cp) >> 1] =
            __floats2half2_rn(sC[r][2 * cp], sC[r][2 * cp + 1]);
    }
}

// ---------------------------------------------------------------------------
// Kernel 3a: coordinate precompute, 4 gaussians per block (R16 version).
// ---------------------------------------------------------------------------
__global__ void __launch_bounds__(256) coord_kernel(
    const float* __restrict__ means, const float* __restrict__ scales,
    const float* __restrict__ rots, const float* __restrict__ transforms,
    const float* __restrict__ proj, const float* __restrict__ W_off,
    const float* __restrict__ b_off)
{
    const int tid = threadIdx.x;
    const int h = tid >> 5;
    const int lane = tid & 31;

    __shared__ float sqm[NHEAD][HDIM];   // per-head token-mean query
    __shared__ float slog[NHEAD][18];    // offset logits
    __shared__ float sW[67 * 18];
    __shared__ float sb[18];
    __shared__ float sP[12];
    __shared__ float sMisc[16];          // 0-2 mean_w, 3-11 R(row major), 12-14 scales

    for (int i = tid; i < 67 * 18; i += 256) sW[i] = W_off[i];
    if (tid < 18) sb[tid] = b_off[tid];
    if (tid >= 32 && tid < 44) sP[tid - 32] = proj[tid - 32];

    for (int gi = 0; gi < 4; gi++) {
        const int g = blockIdx.x * 4 + gi;
        __syncthreads();

        if (tid == 64) {
            float mx = means[g * 3], my = means[g * 3 + 1], mz = means[g * 3 + 2];
            const float* T = transforms + (size_t)g * 16;
            sMisc[0] = T[0] * mx + T[1] * my + T[2]  * mz + T[3];
            sMisc[1] = T[4] * mx + T[5] * my + T[6]  * mz + T[7];
            sMisc[2] = T[8] * mx + T[9] * my + T[10] * mz + T[11];
            float qw = rots[g * 4], qx = rots[g * 4 + 1], qy = rots[g * 4 + 2], qz = rots[g * 4 + 3];
            float inv = rsqrtf(qw * qw + qx * qx + qy * qy + qz * qz);
            qw *= inv; qx *= inv; qy *= inv; qz *= inv;
            sMisc[3]  = 1.f - 2.f * (qy * qy + qz * qz);
            sMisc[4]  = 2.f * (qx * qy - qw * qz);
            sMisc[5]  = 2.f * (qx * qz + qw * qy);
            sMisc[6]  = 2.f * (qx * qy + qw * qz);
            sMisc[7]  = 1.f - 2.f * (qx * qx + qz * qz);
            sMisc[8]  = 2.f * (qy * qz - qw * qx);
            sMisc[9]  = 2.f * (qx * qz - qw * qy);
            sMisc[10] = 2.f * (qy * qz + qw * qx);
            sMisc[11] = 1.f - 2.f * (qx * qx + qy * qy);
            sMisc[12] = scales[g * 3]; sMisc[13] = scales[g * 3 + 1]; sMisc[14] = scales[g * 3 + 2];
        }

        {
            const __half2* qg = g_qh + ((((size_t)g * 3) * ATTN + h * HDIM) >> 1) + lane;
            float2 q0 = __half22float2(qg[0]);
            float2 q1 = __half22float2(qg[ATTN / 2]);
            float2 q2 = __half22float2(qg[ATTN]);
            sqm[h][lane * 2]     = (q0.x + q1.x + q2.x) * (1.0f / 3.0f);
            sqm[h][lane * 2 + 1] = (q0.y + q1.y + q2.y) * (1.0f / 3.0f);
        }
        __syncthreads();

        if (lane < 18) {
            float acc = sb[lane] + sMisc[0] * sW[lane] + sMisc[1] * sW[18 + lane] + sMisc[2] * sW[36 + lane];
            #pragma unroll 8
            for (int c = 0; c < HDIM; c++) acc += sqm[h][c] * sW[(3 + c) * 18 + lane];
            slog[h][lane] = acc;
        }
        __syncwarp();

        if (lane < NK) {
            const int k = lane;
            float s0, s1, s2;
            if (k < 6) {
                s0 = c_fix[k][0]; s1 = c_fix[k][1]; s2 = c_fix[k][2];
            } else {
                int b = (k - 6) * 3;
                s0 = sigm_clamped(slog[h][b])     - 0.5f;
                s1 = sigm_clamped(slog[h][b + 1]) - 0.5f;
                s2 = sigm_clamped(slog[h][b + 2]) - 0.5f;
            }
            float o0 = s0 * sMisc[12], o1 = s1 * sMisc[13], o2 = s2 * sMisc[14];
            float wx = sMisc[3] * o0 + sMisc[6] * o1 + sMisc[9]  * o2 + sMisc[0];
            float wy = sMisc[4] * o0 + sMisc[7] * o1 + sMisc[10] * o2 + sMisc[1];
            float wz = sMisc[5] * o0 + sMisc[8] * o1 + sMisc[11] * o2 + sMisc[2];
            float p0 = sP[0] * wx + sP[1] * wy + sP[2]  * wz + sP[3];
            float p1 = sP[4] * wx + sP[5] * wy + sP[6]  * wz + sP[7];
            float p2 = sP[8] * wx + sP[9] * wy + sP[10] * wz + sP[11];
            float z = fmaxf(p2, 1e-5f);
            float xn = fminf(fmaxf(p0 / z * (1.0f / IMGW), 0.0f), 0.9999f);
            float yn = fminf(fmaxf(p1 / z * (1.0f / IMGH), 0.0f), 0.9999f);
            float x = xn * (float)IMGW - 0.5f;
            float y = yn * (float)IMGH - 0.5f;

            float xf = floorf(x), yf = floorf(y);
            int x0 = (int)xf, y0 = (int)yf;
            float fx = x - xf, fy = y - yf;
            float w00 = (1.f - fx) * (1.f - fy), w10 = fx * (1.f - fy);
            float w01 = (1.f - fx) * fy,         w11 = fx * fy;
            int x1 = x0 + 1, y1 = y0 + 1;
            float vx0 = (x0 >= 0) ? 1.f : 0.f;
            float vx1 = (x1 <= IMGW - 1) ? 1.f : 0.f;
            float vy0 = (y0 >= 0) ? 1.f : 0.f;
            float vy1 = (y1 <= IMGH - 1) ? 1.f : 0.f;
            int cx0 = max(x0, 0), cx1 = min(x1, IMGW - 1);
            int cy0 = max(y0, 0), cy1 = min(y1, IMGH - 1);

            size_t idx = ((size_t)g * NHEAD + h) * NK + k;
            __half2 h00 = __float2half2_rn(w00 * vx0 * vy0);
            __half2 h10 = __float2half2_rn(w10 * vx1 * vy0);
            __half2 h01 = __float2half2_rn(w01 * vx0 * vy1);
            __half2 h11 = __float2half2_rn(w11 * vx1 * vy1);
            uint4 uw;
            uw.x = *(unsigned*)&h00;
            uw.y = *(unsigned*)&h10;
            uw.z = *(unsigned*)&h01;
            uw.w = *(unsigned*)&h11;
            g_wh[idx] = uw;
            int4 o4;
            o4.x = (cy0 * IMGW + cx0) * 512;
            o4.y = (cy0 * IMGW + cx1) * 512;
            o4.z = (cy1 * IMGW + cx0) * 512;
            o4.w = (cy1 * IMGW + cx1) * 512;
            g_o4[idx] = o4;
        }
    }
}

// ---------------------------------------------------------------------------
// Kernel 3b: gather + attention.  ONE WARP per (gaussian, head).
//   Online softmax, half2 HFMA2 corner gather, fp32 butterfly reductions.
// ---------------------------------------------------------------------------
__global__ void __launch_bounds__(256, 4) gather_attn()
{
    const int wid  = (blockIdx.x * 256 + threadIdx.x) >> 5;  // 0..65535
    const int lane = threadIdx.x & 31;
    const int g = wid >> 3;
    const int h = wid & 7;
    const int hidx2 = 2 * (h * 32 + lane);     // half2 offset within pixel record

    const uint4* __restrict__ wp = g_wh + (size_t)wid * NK;
    const int4*  __restrict__ op = g_o4 + (size_t)wid * NK;

    const __half2* qg = g_qh + ((((size_t)g * 3) * ATTN + h * HDIM) >> 1) + lane;
    float2 q0 = __half22float2(qg[0]);
    float2 q1 = __half22float2(qg[ATTN / 2]);
    float2 q2 = __half22float2(qg[ATTN]);
    q0.x *= 0.125f; q0.y *= 0.125f;
    q1.x *= 0.125f; q1.y *= 0.125f;
    q2.x *= 0.125f; q2.y *= 0.125f;

    float sum0 = 0.f, sum1 = 0.f, sum2 = 0.f;
    float oa0 = 0.f, ob0 = 0.f, oa1 = 0.f, ob1 = 0.f, oa2 = 0.f, ob2 = 0.f;

    #pragma unroll
    for (int k = 0; k < NK; k++) {
        uint4 uw = wp[k];                       // warp-uniform broadcast loads
        int4  o  = op[k];
        __half2 kacc = __floats2half2_rn(0.f, 0.f);
        __half2 vacc = __floats2half2_rn(0.f, 0.f);
        {
            float2 raw = *(const float2*)(g_kvh + o.x + hidx2);
            kacc = __hfma2(*(__half2*)&uw.x, *(__half2*)&raw.x, kacc);
            vacc = __hfma2(*(__half2*)&uw.x, *(__half2*)&raw.y, vacc);
        }
        {
            float2 raw = *(const float2*)(g_kvh + o.y + hidx2);
            kacc = __hfma2(*(__half2*)&uw.y, *(__half2*)&raw.x, kacc);
            vacc = __hfma2(*(__half2*)&uw.y, *(__half2*)&raw.y, vacc);
        }
        {
            float2 raw = *(const float2*)(g_kvh + o.z + hidx2);
            kacc = __hfma2(*(__half2*)&uw.z, *(__half2*)&raw.x, kacc);
            vacc = __hfma2(*(__half2*)&uw.z, *(__half2*)&raw.y, vacc);
        }
        {
            float2 raw = *(const float2*)(g_kvh + o.w + hidx2);
            kacc = __hfma2(*(__half2*)&uw.w, *(__half2*)&raw.x, kacc);
            vacc = __hfma2(*(__half2*)&uw.w, *(__half2*)&raw.y, vacc);
        }
        float2 kf = __half22float2(kacc);
        float2 vf = __half22float2(vacc);

        float s0 = warp_sum(q0.x * kf.x + q0.y * kf.y);
        float s1 = warp_sum(q1.x * kf.x + q1.y * kf.y);
        float s2 = warp_sum(q2.x * kf.x + q2.y * kf.y);
        float e0 = __expf(s0);
        float e1 = __expf(s1);
        float e2 = __expf(s2);
        sum0 += e0; oa0 += e0 * vf.x; ob0 += e0 * vf.y;
        sum1 += e1; oa1 += e1 * vf.x; ob1 += e1 * vf.y;
        sum2 += e2; oa2 += e2 * vf.x; ob2 += e2 * vf.y;
    }

    const size_t obase = (((size_t)g * 3) * ATTN + h * HDIM) / 2 + lane;
    float i0 = __fdividef(1.0f, sum0);
    float i1 = __fdividef(1.0f, sum1);
    float i2 = __fdividef(1.0f, sum2);
    g_attnh[obase]            = __floats2half2_rn(oa0 * i0, ob0 * i0);
    g_attnh[obase + ATTN / 2] = __floats2half2_rn(oa1 * i1, ob1 * i1);
    g_attnh[obase + ATTN]     = __floats2half2_rn(oa2 * i2, ob2 * i2);
}

// ---------------------------------------------------------------------------
// Kernel 4: output projection via tensor cores + bias + fp32 residual.
//   out[row,f] = sum_a g_attnh[row,a] * Wout16[a,f] + b_out[f] + feat[row,f]
//   M=24576, K=512, N=32.  Block tile 128 rows x 32 cols; 8 warps x 16 rows,
//   2 col-frags each; K staged 32 at a time.
// ---------------------------------------------------------------------------
__global__ void __launch_bounds__(256) out_gemm_wmma(
    const float* __restrict__ b_out, const float* __restrict__ feat,
    float* __restrict__ out)
{
    __shared__ __align__(16) __half sA[128][40];   // rows x k (32 pad40)
    __shared__ __align__(16) __half sB[32][40];    // k x cols (32 pad40)
    __shared__ __align__(16) float  sC[128][36];   // rows x cols (pad36)

    const int tid  = threadIdx.x;
    const int warp = tid >> 5;
    const int rBase = blockIdx.x * 128;

    wmma::fragment<wmma::accumulator, 16, 16, 16, float> c[2];
    #pragma unroll
    for (int j = 0; j < 2; j++) wmma::fill_fragment(c[j], 0.0f);

    for (int k0 = 0; k0 < ATTN; k0 += 32) {
        // A: 128 rows x 16 half2 from g_attnh
        #pragma unroll
        for (int i = tid; i < 128 * 16; i += 256) {
            int r = i >> 4, cp = i & 15;
            *(__half2*)&sA[r][cp * 2] =
                g_attnh[((size_t)(rBase + r) * ATTN + k0 + cp * 2) >> 1];
        }
        // B: 32 k-rows x 16 half2 from wout16
        #pragma unroll
        for (int i = tid; i < 32 * 16; i += 256) {
            int r = i >> 4, cp = i & 15;
            *(__half2*)&sB[r][cp * 2] =
                *(const __half2*)&g_wout16[(size_t)(k0 + r) * GFD + cp * 2];
        }
        __syncthreads();
        #pragma unroll
        for (int kk = 0; kk < 2; kk++) {
            wmma::fragment<wmma::matrix_a, 16, 16, 16, __half, wmma::row_major> af;
            wmma::load_matrix_sync(af, &sA[warp * 16][kk * 16], 40);
            #pragma unroll
            for (int j = 0; j < 2; j++) {
                wmma::fragment<wmma::matrix_b, 16, 16, 16, __half, wmma::row_major> bf;
                wmma::load_matrix_sync(bf, &sB[kk * 16][j * 16], 40);
                wmma::mma_sync(c[j], af, bf, c[j]);
            }
        }
        __syncthreads();
    }

    #pragma unroll
    for (int j = 0; j < 2; j++)
        wmma::store_matrix_sync(&sC[warp * 16][j * 16], c[j], 36, wmma::mem_row_major);
    __syncthreads();

    for (int idx = tid; idx < 128 * 32; idx += 256) {
        int r = idx >> 5, col = idx & 31;
        int grow = rBase + r;
        out[(size_t)grow * GFD + col] =
            sC[r][col] + b_out[col] + feat[(size_t)grow * GFD + col];
    }
}

// ---------------------------------------------------------------------------
// Launch
// ---------------------------------------------------------------------------
extern "C" void kernel_launch(void* const* d_in, const int* in_sizes, int n_in,
                              void* d_out, int out_size)
{
    const float* means      = (const float*)d_in[0];
    const float* scales     = (const float*)d_in[1];
    const float* rotations  = (const float*)d_in[2];
    const float* features   = (const float*)d_in[3];
    const float* transforms = (const float*)d_in[4];
    const float* projection = (const float*)d_in[5];
    const float* image_feat = (const float*)d_in[6];
    const float* Wq         = (const float*)d_in[7];
    const float* Wk         = (const float*)d_in[8];
    const float* Wv         = (const float*)d_in[9];
    const float* W_off      = (const float*)d_in[10];
    const float* b_off      = (const float*)d_in[11];
    const float* Wout       = (const float*)d_in[12];
    const float* b_out      = (const float*)d_in[13];
    float* out = (float*)d_out;

    // 0) fp32 -> fp16 operand conversion
    convert_fp16<<<(N_CONV + 255) / 256, 256>>>(Wk, Wv, image_feat, features, Wq, Wout);
    // 1) KV feature maps: smem-staged tensor-core GEMM
    kv_gemm_wmma<<<dim3(NPIX / 128, 1024 / 64), 256>>>();
    // 2) Q projection: smem-staged tensor-core GEMM
    q_gemm_wmma<<<dim3(ATTN / 128, NROW / 64), 256>>>();
    // 3a) offsets -> resolved bilinear weights (half2) + corner offsets
    coord_kernel<<<NG / 4, 256>>>(means, scales, rotations, transforms,
                                  projection, W_off, b_off);
    // 3b) barrier-free gather + attention, online softmax (one warp per (g,h))
    gather_attn<<<NG, 256>>>();
    // 4) output projection: tensor cores + bias + residual
    out_gemm_wmma<<<NROW / 128, 256>>>(b_out, features, out);
}